// round 1
// baseline (speedup 1.0000x reference)
#include <cuda_runtime.h>
#include <cstdint>

#define NP 800000
#define EPS 1e-5f

typedef unsigned long long u64;

// -------- global scratch (no allocations allowed) --------
__device__ float g_Y1[(size_t)NP * 64];    // stage-1 pre/post BN (in-place)
__device__ float g_Y2[(size_t)NP * 64];    // conv pre/post BN (in-place)
__device__ float g_Y3[(size_t)NP * 256];   // stage-3 pre-BN
// stats: grp1 sum[0..320) sq[320..640) (cols 0..63 = Y1, 64..319 = YS)
//        grp2 sum[640..704) sq[704..768)
//        grp3 sum[768..1024) sq[1024..1280)
__device__ float g_stats[1280];
// scale/shift: Y1 @0..64, YS @64..320, Y2 @320..384, Y3 @384..640
__device__ float g_scale[640];
__device__ float g_shift[640];

// -------- f32x2 packed-FMA helpers (full-rate fp32 on sm_103a) --------
__device__ __forceinline__ void ffma2(u64 &acc, u64 x, u64 w) {
    asm("fma.rn.f32x2 %0, %1, %2, %0;" : "+l"(acc) : "l"(x), "l"(w));
}
__device__ __forceinline__ u64 dup2(float v) {
    u64 r; asm("mov.b64 %0, {%1, %1};" : "=l"(r) : "r"(__float_as_uint(v))); return r;
}
__device__ __forceinline__ u64 pack2(float a, float b) {
    u64 r; asm("mov.b64 %0, {%1, %2};" : "=l"(r)
               : "r"(__float_as_uint(a)), "r"(__float_as_uint(b))); return r;
}
__device__ __forceinline__ float2 unpack2(u64 v) {
    unsigned lo, hi; asm("mov.b64 {%0, %1}, %2;" : "=r"(lo), "=r"(hi) : "l"(v));
    return make_float2(__uint_as_float(lo), __uint_as_float(hi));
}
__device__ __forceinline__ float wredsum(float v) {
#pragma unroll
    for (int o = 16; o; o >>= 1) v += __shfl_xor_sync(0xffffffffu, v, o);
    return v;
}

__global__ void zero_stats_kernel() {
    int i = blockIdx.x * blockDim.x + threadIdx.x;
    if (i < 1280) g_stats[i] = 0.f;
}

// -------- GEMM1: Y1 = feats@w1+b1 (cols 0..63), YS = feats@ws+bs (cols 64..319 -> d_out) --------
__global__ __launch_bounds__(256) void gemm1_kernel(
    const float* __restrict__ feats, const float* __restrict__ w1, const float* __restrict__ b1,
    const float* __restrict__ ws, const float* __restrict__ bs, float* __restrict__ outYS) {
    extern __shared__ float sm[];
    float* W = sm;               // 64 x 320
    float* bias = sm + 20480;    // 320
    float* sstat = sm + 20800;   // 640
    int t = threadIdx.x;
    for (int i = t; i < 20480; i += 256) {
        int j = i / 320, c = i - j * 320;
        W[i] = (c < 64) ? w1[j * 64 + c] : ws[j * 256 + (c - 64)];
    }
    for (int i = t; i < 320; i += 256) bias[i] = (i < 64) ? b1[i] : bs[i - 64];
    for (int i = t; i < 640; i += 256) sstat[i] = 0.f;
    __syncthreads();

    long row = (long)blockIdx.x * 256 + t;
    float f[64];
    {
        const float4* fr = (const float4*)(feats + row * 64);
#pragma unroll
        for (int i = 0; i < 16; i++) {
            float4 v = fr[i];
            f[4 * i] = v.x; f[4 * i + 1] = v.y; f[4 * i + 2] = v.z; f[4 * i + 3] = v.w;
        }
    }
    int lane = t & 31;
    for (int cg = 0; cg < 80; cg++) {
        int c = cg * 4;
        u64 a01 = pack2(bias[c], bias[c + 1]);
        u64 a23 = pack2(bias[c + 2], bias[c + 3]);
        const float* Wc = W + c;
#pragma unroll
        for (int j = 0; j < 64; j++) {
            ulonglong2 wv = *(const ulonglong2*)(Wc + j * 320);
            u64 xx = dup2(f[j]);
            ffma2(a01, xx, wv.x);
            ffma2(a23, xx, wv.y);
        }
        float2 v01 = unpack2(a01), v23 = unpack2(a23);
        float vals[4] = {v01.x, v01.y, v23.x, v23.y};
#pragma unroll
        for (int q = 0; q < 4; q++) {
            float ssum = wredsum(vals[q]);
            float ssq  = wredsum(vals[q] * vals[q]);
            if (lane == 0) {
                atomicAdd(&sstat[c + q], ssum);
                atomicAdd(&sstat[320 + c + q], ssq);
            }
        }
        if (c < 64)
            *(float4*)&g_Y1[row * 64 + c] = make_float4(vals[0], vals[1], vals[2], vals[3]);
        else
            *(float4*)&outYS[row * 256 + (c - 64)] = make_float4(vals[0], vals[1], vals[2], vals[3]);
    }
    __syncthreads();
    for (int i = t; i < 640; i += 256) atomicAdd(&g_stats[i], sstat[i]);
}

// -------- GEMM3: Y3 = h2 @ w3 + b3 --------
__global__ __launch_bounds__(256) void gemm3_kernel(
    const float* __restrict__ w3, const float* __restrict__ b3) {
    extern __shared__ float sm[];
    float* W = sm;              // 64 x 256
    float* bias = sm + 16384;   // 256
    float* sstat = sm + 16640;  // 512
    int t = threadIdx.x;
    for (int i = t; i < 16384; i += 256) W[i] = w3[i];
    for (int i = t; i < 256; i += 256) bias[i] = b3[i];
    for (int i = t; i < 512; i += 256) sstat[i] = 0.f;
    __syncthreads();

    long row = (long)blockIdx.x * 256 + t;
    float f[64];
    {
        const float4* fr = (const float4*)(g_Y2 + row * 64);
#pragma unroll
        for (int i = 0; i < 16; i++) {
            float4 v = fr[i];
            f[4 * i] = v.x; f[4 * i + 1] = v.y; f[4 * i + 2] = v.z; f[4 * i + 3] = v.w;
        }
    }
    int lane = t & 31;
    for (int cg = 0; cg < 64; cg++) {
        int c = cg * 4;
        u64 a01 = pack2(bias[c], bias[c + 1]);
        u64 a23 = pack2(bias[c + 2], bias[c + 3]);
        const float* Wc = W + c;
#pragma unroll
        for (int j = 0; j < 64; j++) {
            ulonglong2 wv = *(const ulonglong2*)(Wc + j * 256);
            u64 xx = dup2(f[j]);
            ffma2(a01, xx, wv.x);
            ffma2(a23, xx, wv.y);
        }
        float2 v01 = unpack2(a01), v23 = unpack2(a23);
        float vals[4] = {v01.x, v01.y, v23.x, v23.y};
#pragma unroll
        for (int q = 0; q < 4; q++) {
            float ssum = wredsum(vals[q]);
            float ssq  = wredsum(vals[q] * vals[q]);
            if (lane == 0) {
                atomicAdd(&sstat[c + q], ssum);
                atomicAdd(&sstat[256 + c + q], ssq);
            }
        }
        *(float4*)&g_Y3[row * 256 + c] = make_float4(vals[0], vals[1], vals[2], vals[3]);
    }
    __syncthreads();
    for (int i = t; i < 512; i += 256) atomicAdd(&g_stats[768 + i], sstat[i]);
}

// -------- stats -> per-column scale/shift --------
__global__ void finalize_kernel(const float* __restrict__ gamma, const float* __restrict__ beta,
                                int sumOff, int sqOff, int outOff, int cnt) {
    int t = threadIdx.x;
    if (t < cnt) {
        float inv = 1.0f / (float)NP;
        float m = g_stats[sumOff + t] * inv;
        float v = g_stats[sqOff + t] * inv - m * m;
        float sc = rsqrtf(v + EPS) * gamma[t];
        g_scale[outOff + t] = sc;
        g_shift[outOff + t] = beta[t] - m * sc;
    }
}

// -------- in-place BN + relu for [N,64] buffers --------
__global__ __launch_bounds__(256) void bnrelu_kernel(int which) {
    float* Y = which ? g_Y2 : g_Y1;
    int off = which ? 320 : 0;
    long i = (long)blockIdx.x * 256 + threadIdx.x;   // float4 index, total 12.8M
    float4 v = ((float4*)Y)[i];
    int c = (int)(i * 4) & 63;
    float4 sc = *(const float4*)&g_scale[off + c];
    float4 sh = *(const float4*)&g_shift[off + c];
    v.x = fmaxf(fmaf(v.x, sc.x, sh.x), 0.f);
    v.y = fmaxf(fmaf(v.y, sc.y, sh.y), 0.f);
    v.z = fmaxf(fmaf(v.z, sc.z, sh.z), 0.f);
    v.w = fmaxf(fmaf(v.w, sc.w, sh.w), 0.f);
    ((float4*)Y)[i] = v;
}

// -------- subm 3x3 conv: warp-per-point, skip invalid neighbors (uniform) --------
__global__ __launch_bounds__(512) void conv_kernel(
    const int* __restrict__ nbrs, const float* __restrict__ w2, const float* __restrict__ b2) {
    extern __shared__ float sm[];
    float* wsh  = sm;                  // 9*64*64 = 36864
    float* xbuf = sm + 36864;          // 16 warps * 68
    float* sstat = sm + 36864 + 1088;  // 128
    int t = threadIdx.x;
    for (int i = t; i < 9216; i += 512) ((float4*)wsh)[i] = ((const float4*)w2)[i];
    for (int i = t; i < 128; i += 512) sstat[i] = 0.f;
    __syncthreads();

    int wlocal = t >> 5, lane = t & 31;
    float* xw = xbuf + wlocal * 68;
    int gw = blockIdx.x * 16 + wlocal;
    int nW = gridDim.x * 16;
    float2 bv = ((const float2*)b2)[lane];
    float ps0 = 0.f, pq0 = 0.f, ps1 = 0.f, pq1 = 0.f;

    for (int i = gw; i < NP; i += nW) {
        int nb = (lane < 9) ? nbrs[i * 9 + lane] : -1;
        float a0 = bv.x, a1 = bv.y;
#pragma unroll
        for (int k = 0; k < 9; k++) {
            int idx = __shfl_sync(0xffffffffu, nb, k);
            if (idx >= 0) {
                float2 xv = ((const float2*)(g_Y1 + (long)idx * 64))[lane];
                __syncwarp();
                ((float2*)xw)[lane] = xv;
                __syncwarp();
                const float* wk = wsh + k * 4096;
#pragma unroll
                for (int j4 = 0; j4 < 16; j4++) {
                    float4 x4 = *(const float4*)(xw + 4 * j4);
                    float2 w;
                    w = *(const float2*)(wk + (4 * j4 + 0) * 64 + 2 * lane);
                    a0 = fmaf(x4.x, w.x, a0); a1 = fmaf(x4.x, w.y, a1);
                    w = *(const float2*)(wk + (4 * j4 + 1) * 64 + 2 * lane);
                    a0 = fmaf(x4.y, w.x, a0); a1 = fmaf(x4.y, w.y, a1);
                    w = *(const float2*)(wk + (4 * j4 + 2) * 64 + 2 * lane);
                    a0 = fmaf(x4.z, w.x, a0); a1 = fmaf(x4.z, w.y, a1);
                    w = *(const float2*)(wk + (4 * j4 + 3) * 64 + 2 * lane);
                    a0 = fmaf(x4.w, w.x, a0); a1 = fmaf(x4.w, w.y, a1);
                }
            }
        }
        ((float2*)(g_Y2 + (long)i * 64))[lane] = make_float2(a0, a1);
        ps0 += a0; pq0 = fmaf(a0, a0, pq0);
        ps1 += a1; pq1 = fmaf(a1, a1, pq1);
    }
    int c0 = 2 * lane;
    atomicAdd(&sstat[c0], ps0);      atomicAdd(&sstat[c0 + 1], ps1);
    atomicAdd(&sstat[64 + c0], pq0); atomicAdd(&sstat[64 + c0 + 1], pq1);
    __syncthreads();
    for (int i = t; i < 128; i += 512) atomicAdd(&g_stats[640 + i], sstat[i]);
}

// -------- final: out = BN(YS) + relu(BN(Y3)) --------
__global__ __launch_bounds__(256) void final_kernel(float* __restrict__ out) {
    long i = (long)blockIdx.x * 256 + threadIdx.x;   // float4 index, total 51.2M
    float4 ys = ((float4*)out)[i];
    float4 y3 = *(const float4*)&g_Y3[i * 4];
    int c = (int)(i * 4) & 255;
    float4 scS = *(const float4*)&g_scale[64 + c];
    float4 shS = *(const float4*)&g_shift[64 + c];
    float4 sc3 = *(const float4*)&g_scale[384 + c];
    float4 sh3 = *(const float4*)&g_shift[384 + c];
    float4 r;
    r.x = fmaf(ys.x, scS.x, shS.x) + fmaxf(fmaf(y3.x, sc3.x, sh3.x), 0.f);
    r.y = fmaf(ys.y, scS.y, shS.y) + fmaxf(fmaf(y3.y, sc3.y, sh3.y), 0.f);
    r.z = fmaf(ys.z, scS.z, shS.z) + fmaxf(fmaf(y3.z, sc3.z, sh3.z), 0.f);
    r.w = fmaf(ys.w, scS.w, shS.w) + fmaxf(fmaf(y3.w, sc3.w, sh3.w), 0.f);
    ((float4*)out)[i] = r;
}

extern "C" void kernel_launch(void* const* d_in, const int* in_sizes, int n_in,
                              void* d_out, int out_size) {
    const float* feats = (const float*)d_in[0];
    const int*   nbrs  = (const int*)d_in[1];
    const float* w1  = (const float*)d_in[2];
    const float* b1  = (const float*)d_in[3];
    const float* g1  = (const float*)d_in[4];
    const float* be1 = (const float*)d_in[5];
    const float* w2  = (const float*)d_in[6];
    const float* b2  = (const float*)d_in[7];
    const float* g2  = (const float*)d_in[8];
    const float* be2 = (const float*)d_in[9];
    const float* w3  = (const float*)d_in[10];
    const float* b3  = (const float*)d_in[11];
    const float* g3  = (const float*)d_in[12];
    const float* be3 = (const float*)d_in[13];
    const float* wsp = (const float*)d_in[14];
    const float* bsp = (const float*)d_in[15];
    const float* gsp = (const float*)d_in[16];
    const float* besp= (const float*)d_in[17];
    float* out = (float*)d_out;

    cudaFuncSetAttribute(gemm1_kernel, cudaFuncAttributeMaxDynamicSharedMemorySize, 85760);
    cudaFuncSetAttribute(gemm3_kernel, cudaFuncAttributeMaxDynamicSharedMemorySize, 68608);
    cudaFuncSetAttribute(conv_kernel,  cudaFuncAttributeMaxDynamicSharedMemorySize, 152320);

    zero_stats_kernel<<<5, 256>>>();
    gemm1_kernel<<<3125, 256, 85760>>>(feats, w1, b1, wsp, bsp, out);
    finalize_kernel<<<1, 64 >>>(g1, be1, 0, 320, 0, 64);
    finalize_kernel<<<1, 256>>>(gsp, besp, 64, 384, 64, 256);
    bnrelu_kernel<<<50000, 256>>>(0);
    conv_kernel<<<1184, 512, 152320>>>(nbrs, w2, b2);
    finalize_kernel<<<1, 64 >>>(g2, be2, 640, 704, 320, 64);
    bnrelu_kernel<<<50000, 256>>>(1);
    gemm3_kernel<<<3125, 256, 68608>>>(w3, b3);
    finalize_kernel<<<1, 256>>>(g3, be3, 768, 1024, 384, 256);
    final_kernel<<<200000, 256>>>(out);
}

// round 3
// speedup vs baseline: 1.2196x; 1.2196x over previous
#include <cuda_runtime.h>

#define NP 800000
#define EPS 1e-5f
typedef unsigned long long u64;

// ---------------- global scratch ----------------
__device__ float g_Y1[(size_t)NP * 64];    // stage-1 pre-BN (raw)
__device__ float g_Y2[(size_t)NP * 64];    // conv pre-BN (raw)
__device__ float g_Y3[(size_t)NP * 256];   // stage-3 pre-BN (raw)
__device__ int2  g_list[8][NP];            // per-offset compacted (out, src)
__device__ int   g_cnt[8];
// stats layout: Y1 sum[0,64) sq[64,128); YS sum[128,384) sq[384,640);
//               Y2 sum[640,704) sq[704,768); Y3 sum[768,1024) sq[1024,1280)
__device__ float g_stats[1280];
// scale/shift: Y1 @0..64, YS @64..320, Y2 @320..384, Y3 @384..640
__device__ float g_scale[640];
__device__ float g_shift[640];

// ---------------- f32x2 helpers ----------------
__device__ __forceinline__ void ffma2(u64 &acc, u64 x, u64 w) {
    asm("fma.rn.f32x2 %0, %1, %2, %0;" : "+l"(acc) : "l"(x), "l"(w));
}
__device__ __forceinline__ u64 pack2(float a, float b) {
    u64 r; asm("mov.b64 %0, {%1, %2};" : "=l"(r)
               : "r"(__float_as_uint(a)), "r"(__float_as_uint(b))); return r;
}
__device__ __forceinline__ float2 unpack2(u64 v) {
    unsigned lo, hi; asm("mov.b64 {%0, %1}, %2;" : "=r"(lo), "=r"(hi) : "l"(v));
    return make_float2(__uint_as_float(lo), __uint_as_float(hi));
}

// dot of x-row (packed pairs, 64 floats) against 4 transposed-weight columns.
// WT layout: WT[c*64 + j]; all lanes read same address -> broadcast LDS.
__device__ __forceinline__ float4 dot4(const float* __restrict__ WT,
                                       const u64* __restrict__ xp, int c) {
    const ulonglong2* w0 = (const ulonglong2*)(WT + (c + 0) * 64);
    const ulonglong2* w1 = (const ulonglong2*)(WT + (c + 1) * 64);
    const ulonglong2* w2 = (const ulonglong2*)(WT + (c + 2) * 64);
    const ulonglong2* w3 = (const ulonglong2*)(WT + (c + 3) * 64);
    u64 a0 = 0, a1 = 0, a2 = 0, a3 = 0;
#pragma unroll
    for (int m = 0; m < 16; m++) {
        ulonglong2 v0 = w0[m]; ffma2(a0, xp[2*m], v0.x); ffma2(a0, xp[2*m+1], v0.y);
        ulonglong2 v1 = w1[m]; ffma2(a1, xp[2*m], v1.x); ffma2(a1, xp[2*m+1], v1.y);
        ulonglong2 v2 = w2[m]; ffma2(a2, xp[2*m], v2.x); ffma2(a2, xp[2*m+1], v2.y);
        ulonglong2 v3 = w3[m]; ffma2(a3, xp[2*m], v3.x); ffma2(a3, xp[2*m+1], v3.y);
    }
    float2 p0 = unpack2(a0), p1 = unpack2(a1), p2 = unpack2(a2), p3 = unpack2(a3);
    return make_float4(p0.x + p0.y, p1.x + p1.y, p2.x + p2.y, p3.x + p3.y);
}

// load a 64-float row, apply BN scale/shift + relu, pack into 32 u64 pairs
__device__ __forceinline__ void load_row_bn(const float* __restrict__ row,
        const float* __restrict__ sc, const float* __restrict__ sh, u64* xp) {
#pragma unroll
    for (int m = 0; m < 16; m++) {
        float4 v = *(const float4*)(row + 4 * m);
        float4 s = *(const float4*)(sc + 4 * m);
        float4 b = *(const float4*)(sh + 4 * m);
        float x0 = fmaxf(fmaf(v.x, s.x, b.x), 0.f);
        float x1 = fmaxf(fmaf(v.y, s.y, b.y), 0.f);
        float x2 = fmaxf(fmaf(v.z, s.z, b.z), 0.f);
        float x3 = fmaxf(fmaf(v.w, s.w, b.w), 0.f);
        xp[2*m] = pack2(x0, x1); xp[2*m+1] = pack2(x2, x3);
    }
}

__global__ void zero_kernel() {
    int i = blockIdx.x * blockDim.x + threadIdx.x;
    if (i < 1280) g_stats[i] = 0.f;
    if (i < 8) g_cnt[i] = 0;
}

// ---------------- GEMM1: Y1 = feats@w1+b1 ; YS = feats@ws+bs (-> d_out) ----------------
__global__ __launch_bounds__(256) void gemm1_kernel(
    const float* __restrict__ feats, const float* __restrict__ w1, const float* __restrict__ b1,
    const float* __restrict__ ws, const float* __restrict__ bs, float* __restrict__ outYS) {
    extern __shared__ float sm[];
    float* WT = sm;              // 320 cols x 64 (transposed)
    float* bias = sm + 20480;    // 320
    int t = threadIdx.x;
    for (int i = t; i < 20480; i += 256) {
        int c = i >> 6, j = i & 63;
        WT[i] = (c < 64) ? w1[j * 64 + c] : ws[j * 256 + (c - 64)];
    }
    for (int i = t; i < 320; i += 256) bias[i] = (i < 64) ? b1[i] : bs[i - 64];
    __syncthreads();

    long row = (long)blockIdx.x * 256 + t;
    u64 xp[32];
    const ulonglong2* xr = (const ulonglong2*)(feats + row * 64);
#pragma unroll
    for (int m = 0; m < 16; m++) { ulonglong2 v = xr[m]; xp[2*m] = v.x; xp[2*m+1] = v.y; }
    float* y1r = g_Y1 + row * 64;
    float* ysr = outYS + row * 256;
#pragma unroll 1
    for (int cq = 0; cq < 80; cq++) {
        int c = cq * 4;
        float4 r = dot4(WT, xp, c);
        r.x += bias[c]; r.y += bias[c+1]; r.z += bias[c+2]; r.w += bias[c+3];
        if (c < 64) *(float4*)(y1r + c) = r;
        else        *(float4*)(ysr + (c - 64)) = r;
    }
}

// ---------------- column stats (sum, sumsq) ----------------
// which: 1 -> g_Y1, 2 -> g_Y2, 3 -> g_Y3, 0 -> use Yin (d_out).
// G = ncols/4 column-groups; thread t owns colgroup t%G, strides rows.
__global__ __launch_bounds__(256) void stats_kernel(const float* __restrict__ Yin,
                                                    int which, int G, int statOff) {
    const float* Y = (which == 1) ? g_Y1 : (which == 2) ? g_Y2 : (which == 3) ? g_Y3 : Yin;
    __shared__ float s[512];
    int t = threadIdx.x;
    int ncols = G * 4;
    for (int i = t; i < 2 * ncols; i += 256) s[i] = 0.f;
    __syncthreads();
    int cg = t % G;
    int rpb = 256 / G;
    long r = (long)blockIdx.x * rpb + t / G;
    long stride = (long)gridDim.x * rpb;
    float s0=0,s1=0,s2=0,s3=0,q0=0,q1=0,q2=0,q3=0;
    for (; r < NP; r += stride) {
        float4 v = *(const float4*)(Y + r * ncols + cg * 4);
        s0 += v.x; q0 = fmaf(v.x, v.x, q0);
        s1 += v.y; q1 = fmaf(v.y, v.y, q1);
        s2 += v.z; q2 = fmaf(v.z, v.z, q2);
        s3 += v.w; q3 = fmaf(v.w, v.w, q3);
    }
    int c = cg * 4;
    atomicAdd(&s[c+0], s0); atomicAdd(&s[c+1], s1);
    atomicAdd(&s[c+2], s2); atomicAdd(&s[c+3], s3);
    atomicAdd(&s[ncols+c+0], q0); atomicAdd(&s[ncols+c+1], q1);
    atomicAdd(&s[ncols+c+2], q2); atomicAdd(&s[ncols+c+3], q3);
    __syncthreads();
    for (int i = t; i < 2 * ncols; i += 256) atomicAdd(&g_stats[statOff + i], s[i]);
}

__global__ void finalize_kernel(const float* __restrict__ gamma, const float* __restrict__ beta,
                                int sumOff, int sqOff, int outOff, int cnt) {
    int t = threadIdx.x;
    if (t < cnt) {
        float inv = 1.0f / (float)NP;
        float m = g_stats[sumOff + t] * inv;
        float v = g_stats[sqOff + t] * inv - m * m;
        float sc = rsqrtf(v + EPS) * gamma[t];
        g_scale[outOff + t] = sc;
        g_shift[outOff + t] = beta[t] - m * sc;
    }
}

// ---------------- compaction: per-offset (out, src) lists ----------------
__global__ __launch_bounds__(256) void compact_kernel(const int* __restrict__ nbrs) {
    __shared__ int scnt[8], sbase[8], woff[8][8];
    int t = threadIdx.x, w = t >> 5, lane = t & 31;
    if (t < 8) scnt[t] = 0;
    __syncthreads();
    int i = blockIdx.x * 256 + t;  // grid 3125 * 256 == NP exactly
    int nb[8];
    {
        int kk = 0;
#pragma unroll
        for (int k = 0; k < 9; k++) {
            if (k == 4) continue;
            nb[kk++] = nbrs[i * 9 + k];
        }
    }
    unsigned ball[8];
#pragma unroll
    for (int k = 0; k < 8; k++) {
        unsigned m = __ballot_sync(0xffffffffu, nb[k] >= 0);
        ball[k] = m;
        if (lane == 0) woff[k][w] = atomicAdd(&scnt[k], __popc(m));
    }
    __syncthreads();
    if (t < 8) sbase[t] = atomicAdd(&g_cnt[t], scnt[t]);
    __syncthreads();
#pragma unroll
    for (int k = 0; k < 8; k++) {
        if (nb[k] >= 0) {
            int r = __popc(ball[k] & ((1u << lane) - 1u));
            g_list[k][sbase[k] + woff[k][w] + r] = make_int2(i, nb[k]);
        }
    }
}

// ---------------- conv center tap: Y2 = b2 + bnrelu(Y1) @ w2[4] ----------------
__global__ __launch_bounds__(256) void conv_center_kernel(
    const float* __restrict__ w2, const float* __restrict__ b2) {
    extern __shared__ float sm[];
    float* WT = sm;            // 64x64 transposed
    float* bias = sm + 4096;   // 64
    float* sc = sm + 4160;     // 64
    float* sh = sm + 4224;     // 64
    int t = threadIdx.x;
    for (int i = t; i < 4096; i += 256) {
        int c = i >> 6, j = i & 63;
        WT[i] = w2[4 * 4096 + j * 64 + c];
    }
    if (t < 64) { bias[t] = b2[t]; sc[t] = g_scale[t]; sh[t] = g_shift[t]; }
    __syncthreads();

    long row = (long)blockIdx.x * 256 + t;
    u64 xp[32];
    load_row_bn(g_Y1 + row * 64, sc, sh, xp);
    float* yr = g_Y2 + row * 64;
#pragma unroll 1
    for (int cq = 0; cq < 16; cq++) {
        int c = cq * 4;
        float4 r = dot4(WT, xp, c);
        r.x += bias[c]; r.y += bias[c+1]; r.z += bias[c+2]; r.w += bias[c+3];
        *(float4*)(yr + c) = r;
    }
}

// ---------------- conv non-center tap kk (8 sequential launches) ----------------
__global__ __launch_bounds__(256) void convk_kernel(const float* __restrict__ w2, int kk) {
    extern __shared__ float sm[];
    float* WT = sm;           // 64x64 transposed
    float* sc = sm + 4096;
    float* sh = sm + 4160;
    int tap = (kk < 4) ? kk : kk + 1;
    int t = threadIdx.x;
    for (int i = t; i < 4096; i += 256) {
        int c = i >> 6, j = i & 63;
        WT[i] = w2[tap * 4096 + j * 64 + c];
    }
    if (t < 64) { sc[t] = g_scale[t]; sh[t] = g_shift[t]; }
    __syncthreads();

    int n = g_cnt[kk];
    for (long e = (long)blockIdx.x * 256 + t; e < n; e += (long)gridDim.x * 256) {
        int2 ent = g_list[kk][e];
        u64 xp[32];
        load_row_bn(g_Y1 + (long)ent.y * 64, sc, sh, xp);
        float* yr = g_Y2 + (long)ent.x * 64;
#pragma unroll 1
        for (int cq = 0; cq < 16; cq++) {
            int c = cq * 4;
            float4 r = dot4(WT, xp, c);
            float4 y = *(float4*)(yr + c);
            y.x += r.x; y.y += r.y; y.z += r.z; y.w += r.w;
            *(float4*)(yr + c) = y;
        }
    }
}

// ---------------- GEMM3: Y3 = bnrelu(Y2) @ w3 + b3 ----------------
__global__ __launch_bounds__(256) void gemm3_kernel(
    const float* __restrict__ w3, const float* __restrict__ b3) {
    extern __shared__ float sm[];
    float* WT = sm;              // 256 cols x 64 transposed
    float* bias = sm + 16384;    // 256
    float* sc = sm + 16640;      // 64
    float* sh = sm + 16704;      // 64
    int t = threadIdx.x;
    for (int i = t; i < 16384; i += 256) {
        int c = i >> 6, j = i & 63;
        WT[i] = w3[j * 256 + c];
    }
    for (int i = t; i < 256; i += 256) bias[i] = b3[i];
    if (t < 64) { sc[t] = g_scale[320 + t]; sh[t] = g_shift[320 + t]; }
    __syncthreads();

    long row = (long)blockIdx.x * 256 + t;
    u64 xp[32];
    load_row_bn(g_Y2 + row * 64, sc, sh, xp);
    float* yr = g_Y3 + row * 256;
#pragma unroll 1
    for (int cq = 0; cq < 64; cq++) {
        int c = cq * 4;
        float4 r = dot4(WT, xp, c);
        r.x += bias[c]; r.y += bias[c+1]; r.z += bias[c+2]; r.w += bias[c+3];
        *(float4*)(yr + c) = r;
    }
}

// ---------------- final: out = BN(YS) + relu(BN(Y3)) ----------------
__global__ __launch_bounds__(256) void final_kernel(float* __restrict__ out) {
    long i = (long)blockIdx.x * 256 + threadIdx.x;   // float4 index, 51.2M total
    float4 ys = ((float4*)out)[i];
    float4 y3 = *(const float4*)&g_Y3[i * 4];
    int c = (int)(i * 4) & 255;
    float4 scS = *(const float4*)&g_scale[64 + c];
    float4 shS = *(const float4*)&g_shift[64 + c];
    float4 sc3 = *(const float4*)&g_scale[384 + c];
    float4 sh3 = *(const float4*)&g_shift[384 + c];
    float4 r;
    r.x = fmaf(ys.x, scS.x, shS.x) + fmaxf(fmaf(y3.x, sc3.x, sh3.x), 0.f);
    r.y = fmaf(ys.y, scS.y, shS.y) + fmaxf(fmaf(y3.y, sc3.y, sh3.y), 0.f);
    r.z = fmaf(ys.z, scS.z, shS.z) + fmaxf(fmaf(y3.z, sc3.z, sh3.z), 0.f);
    r.w = fmaf(ys.w, scS.w, shS.w) + fmaxf(fmaf(y3.w, sc3.w, sh3.w), 0.f);
    ((float4*)out)[i] = r;
}

extern "C" void kernel_launch(void* const* d_in, const int* in_sizes, int n_in,
                              void* d_out, int out_size) {
    const float* feats = (const float*)d_in[0];
    const int*   nbrs  = (const int*)d_in[1];
    const float* w1  = (const float*)d_in[2];
    const float* b1  = (const float*)d_in[3];
    const float* g1  = (const float*)d_in[4];
    const float* be1 = (const float*)d_in[5];
    const float* w2  = (const float*)d_in[6];
    const float* b2  = (const float*)d_in[7];
    const float* g2  = (const float*)d_in[8];
    const float* be2 = (const float*)d_in[9];
    const float* w3  = (const float*)d_in[10];
    const float* b3  = (const float*)d_in[11];
    const float* g3  = (const float*)d_in[12];
    const float* be3 = (const float*)d_in[13];
    const float* wsp = (const float*)d_in[14];
    const float* bsp = (const float*)d_in[15];
    const float* gsp = (const float*)d_in[16];
    const float* besp= (const float*)d_in[17];
    float* out = (float*)d_out;

    cudaFuncSetAttribute(gemm1_kernel, cudaFuncAttributeMaxDynamicSharedMemorySize, 83200);
    cudaFuncSetAttribute(gemm3_kernel, cudaFuncAttributeMaxDynamicSharedMemorySize, 67072);

    zero_kernel<<<6, 256>>>();
    gemm1_kernel<<<3125, 256, 83200>>>(feats, w1, b1, wsp, bsp, out);
    stats_kernel<<<1184, 256>>>(nullptr, 1, 16, 0);        // Y1 stats
    finalize_kernel<<<1, 64>>>(g1, be1, 0, 64, 0, 64);
    compact_kernel<<<3125, 256>>>(nbrs);
    conv_center_kernel<<<3125, 256, 17152>>>(w2, b2);
    for (int kk = 0; kk < 8; kk++)
        convk_kernel<<<1184, 256, 16896>>>(w2, kk);
    stats_kernel<<<1184, 256>>>(nullptr, 2, 16, 640);      // Y2 stats
    finalize_kernel<<<1, 64>>>(g2, be2, 640, 704, 320, 64);
    gemm3_kernel<<<3125, 256, 67072>>>(w3, b3);
    stats_kernel<<<1184, 256>>>(out, 0, 64, 128);          // YS stats (d_out)
    stats_kernel<<<1184, 256>>>(nullptr, 3, 64, 768);      // Y3 stats
    finalize_kernel<<<1, 256>>>(gsp, besp, 128, 384, 64, 256);
    finalize_kernel<<<1, 256>>>(g3, be3, 768, 1024, 384, 256);
    final_kernel<<<200000, 256>>>(out);
}